// round 4
// baseline (speedup 1.0000x reference)
#include <cuda_runtime.h>
#include <stdint.h>
#include <stddef.h>

#define D 128
#define D4 (D/4)          // 32 float4 per node row

// ---------------------------------------------------------------------------
// Fused kernel.
//  Phase 1: 4-edge chunks per warp, int4-vectorized + software-pipelined
//           index loads. out_ee gather-copy + fused out_ex linear.
//  Phase 2: warp-per-node copy + 2-class linear.
// ---------------------------------------------------------------------------
__global__ void __launch_bounds__(256, 4) gcn_fused_kernel(
    const float* __restrict__ x,
    const int*   __restrict__ ei,     // [2,E] int32
    const float* __restrict__ Wn,     // [D,2]
    const float* __restrict__ bn,     // [2]
    const float* __restrict__ We,     // [2D,2]
    const float* __restrict__ be,     // [2]
    float* __restrict__ out_ne,
    float* __restrict__ out_nx,
    float* __restrict__ out_ee,
    float* __restrict__ out_ex,
    int n_nodes, int n_edges)
{
    const int lane   = threadIdx.x & 31;
    const int warp   = (blockIdx.x * blockDim.x + threadIdx.x) >> 5;
    const int nwarps = (gridDim.x * blockDim.x) >> 5;

    // per-lane We rows (src half / dst half)
    float ws[8], wd[8];
    #pragma unroll
    for (int j = 0; j < 4; ++j) {
        ws[j*2+0] = We[(lane*4+j)*2 + 0];
        ws[j*2+1] = We[(lane*4+j)*2 + 1];
        wd[j*2+0] = We[(128 + lane*4+j)*2 + 0];
        wd[j*2+1] = We[(128 + lane*4+j)*2 + 1];
    }
    const float eb0 = be[0], eb1 = be[1];

    // Process one 4-edge chunk c (edges c*4 .. c*4+3) given its indices.
    #define CHUNK_BODY(sc, dc)                                                   \
    {                                                                            \
        const float4 vs0 = __ldg((const float4*)(x + (size_t)(sc).x * D) + lane);\
        const float4 vd0 = __ldg((const float4*)(x + (size_t)(dc).x * D) + lane);\
        const float4 vs1 = __ldg((const float4*)(x + (size_t)(sc).y * D) + lane);\
        const float4 vd1 = __ldg((const float4*)(x + (size_t)(dc).y * D) + lane);\
        const float4 vs2 = __ldg((const float4*)(x + (size_t)(sc).z * D) + lane);\
        const float4 vd2 = __ldg((const float4*)(x + (size_t)(dc).z * D) + lane);\
        const float4 vs3 = __ldg((const float4*)(x + (size_t)(sc).w * D) + lane);\
        const float4 vd3 = __ldg((const float4*)(x + (size_t)(dc).w * D) + lane);\
        float4* o = (float4*)(out_ee + (size_t)c * (8*D));                       \
        __stcs(o +   0 + lane, vs0);  __stcs(o +  D4 + lane, vd0);               \
        __stcs(o +  64 + lane, vs1);  __stcs(o +  96 + lane, vd1);               \
        __stcs(o + 128 + lane, vs2);  __stcs(o + 160 + lane, vd2);               \
        __stcs(o + 192 + lane, vs3);  __stcs(o + 224 + lane, vd3);               \
        float a0[4], a1[4];                                                      \
        a0[0] = vs0.x*ws[0]+vs0.y*ws[2]+vs0.z*ws[4]+vs0.w*ws[6]                  \
              + vd0.x*wd[0]+vd0.y*wd[2]+vd0.z*wd[4]+vd0.w*wd[6];                 \
        a1[0] = vs0.x*ws[1]+vs0.y*ws[3]+vs0.z*ws[5]+vs0.w*ws[7]                  \
              + vd0.x*wd[1]+vd0.y*wd[3]+vd0.z*wd[5]+vd0.w*wd[7];                 \
        a0[1] = vs1.x*ws[0]+vs1.y*ws[2]+vs1.z*ws[4]+vs1.w*ws[6]                  \
              + vd1.x*wd[0]+vd1.y*wd[2]+vd1.z*wd[4]+vd1.w*wd[6];                 \
        a1[1] = vs1.x*ws[1]+vs1.y*ws[3]+vs1.z*ws[5]+vs1.w*ws[7]                  \
              + vd1.x*wd[1]+vd1.y*wd[3]+vd1.z*wd[5]+vd1.w*wd[7];                 \
        a0[2] = vs2.x*ws[0]+vs2.y*ws[2]+vs2.z*ws[4]+vs2.w*ws[6]                  \
              + vd2.x*wd[0]+vd2.y*wd[2]+vd2.z*wd[4]+vd2.w*wd[6];                 \
        a1[2] = vs2.x*ws[1]+vs2.y*ws[3]+vs2.z*ws[5]+vs2.w*ws[7]                  \
              + vd2.x*wd[1]+vd2.y*wd[3]+vd2.z*wd[5]+vd2.w*wd[7];                 \
        a0[3] = vs3.x*ws[0]+vs3.y*ws[2]+vs3.z*ws[4]+vs3.w*ws[6]                  \
              + vd3.x*wd[0]+vd3.y*wd[2]+vd3.z*wd[4]+vd3.w*wd[6];                 \
        a1[3] = vs3.x*ws[1]+vs3.y*ws[3]+vs3.z*ws[5]+vs3.w*ws[7]                  \
              + vd3.x*wd[1]+vd3.y*wd[3]+vd3.z*wd[5]+vd3.w*wd[7];                 \
        _Pragma("unroll")                                                        \
        for (int o2 = 16; o2; o2 >>= 1) {                                        \
            _Pragma("unroll")                                                    \
            for (int i = 0; i < 4; ++i) {                                        \
                a0[i] += __shfl_xor_sync(0xffffffffu, a0[i], o2);                \
                a1[i] += __shfl_xor_sync(0xffffffffu, a1[i], o2);                \
            }                                                                    \
        }                                                                        \
        if (lane == 0) {                                                         \
            float4* eo = (float4*)(out_ex + (size_t)c * 8);                      \
            __stcs(eo + 0, make_float4(a0[0]+eb0, a1[0]+eb1, a0[1]+eb0, a1[1]+eb1)); \
            __stcs(eo + 1, make_float4(a0[2]+eb0, a1[2]+eb1, a0[3]+eb0, a1[3]+eb1)); \
        }                                                                        \
    }

    const int nchunks = n_edges >> 2;

    if ((n_edges & 3) == 0) {
        // Fast path: both index halves int4-aligned. Software-pipelined.
        const int4* eis = (const int4*)ei;
        const int4* eid = (const int4*)(ei + n_edges);
        int c = warp;
        if (c < nchunks) {
            int4 sc = __ldg(eis + c);
            int4 dc = __ldg(eid + c);
            while (true) {
                const int cn = c + nwarps;
                int4 scn, dcn;
                if (cn < nchunks) {               // prefetch next chunk's indices
                    scn = __ldg(eis + cn);
                    dcn = __ldg(eid + cn);
                }
                CHUNK_BODY(sc, dc)
                if (cn >= nchunks) break;
                c = cn; sc = scn; dc = dcn;
            }
        }
    } else {
        // Generic path: scalar index loads.
        for (int c = warp; c < nchunks; c += nwarps) {
            const int e0 = c * 4;
            int4 sc = make_int4(ei[e0], ei[e0+1], ei[e0+2], ei[e0+3]);
            int4 dc = make_int4(ei[n_edges+e0], ei[n_edges+e0+1],
                                ei[n_edges+e0+2], ei[n_edges+e0+3]);
            CHUNK_BODY(sc, dc)
        }
        // Tail edges — warp 0.
        if (warp == 0) {
            for (int e = nchunks * 4; e < n_edges; ++e) {
                const int s = ei[e];
                const int d = ei[n_edges + e];
                const float4 vs = __ldg((const float4*)(x + (size_t)s * D) + lane);
                const float4 vd = __ldg((const float4*)(x + (size_t)d * D) + lane);
                float4* o = (float4*)(out_ee + (size_t)e * (2*D));
                __stcs(o + lane, vs);
                __stcs(o + D4 + lane, vd);
                float a0 = vs.x*ws[0]+vs.y*ws[2]+vs.z*ws[4]+vs.w*ws[6]
                         + vd.x*wd[0]+vd.y*wd[2]+vd.z*wd[4]+vd.w*wd[6];
                float a1 = vs.x*ws[1]+vs.y*ws[3]+vs.z*ws[5]+vs.w*ws[7]
                         + vd.x*wd[1]+vd.y*wd[3]+vd.z*wd[5]+vd.w*wd[7];
                #pragma unroll
                for (int o2 = 16; o2; o2 >>= 1) {
                    a0 += __shfl_xor_sync(0xffffffffu, a0, o2);
                    a1 += __shfl_xor_sync(0xffffffffu, a1, o2);
                }
                if (lane == 0) {
                    out_ex[(size_t)e*2 + 0] = a0 + eb0;
                    out_ex[(size_t)e*2 + 1] = a1 + eb1;
                }
            }
        }
    }
    #undef CHUNK_BODY

    // ================= Phase 2: nodes =================
    float w[8];
    #pragma unroll
    for (int j = 0; j < 4; ++j) {
        w[j*2+0] = Wn[(lane*4+j)*2 + 0];
        w[j*2+1] = Wn[(lane*4+j)*2 + 1];
    }
    const float nb0 = bn[0], nb1 = bn[1];

    for (int n = warp; n < n_nodes; n += nwarps) {
        const float4 v = __ldg((const float4*)(x + (size_t)n * D) + lane);
        __stcs((float4*)(out_ne + (size_t)n * D) + lane, v);

        float a0 = v.x*w[0] + v.y*w[2] + v.z*w[4] + v.w*w[6];
        float a1 = v.x*w[1] + v.y*w[3] + v.z*w[5] + v.w*w[7];
        #pragma unroll
        for (int o = 16; o; o >>= 1) {
            a0 += __shfl_xor_sync(0xffffffffu, a0, o);
            a1 += __shfl_xor_sync(0xffffffffu, a1, o);
        }
        if (lane == 0) {
            out_nx[(size_t)n*2 + 0] = a0 + nb0;
            out_nx[(size_t)n*2 + 1] = a1 + nb1;
        }
    }
}

extern "C" void kernel_launch(void* const* d_in, const int* in_sizes, int n_in,
                              void* d_out, int out_size)
{
    // Bind inputs by element count (bn before be among the two size-2 inputs).
    const float* x  = 0;
    const int*   ei = 0;
    const float* Wn = 0;
    const float* bn = 0;
    const float* We = 0;
    const float* be = 0;
    int ei_elems = 0, x_elems = 0;

    for (int i = 0; i < n_in; ++i) {
        const int sz = in_sizes[i];
        if (sz == 2) {
            if (!bn) bn = (const float*)d_in[i];
            else     be = (const float*)d_in[i];
        } else if (sz == 256) {
            Wn = (const float*)d_in[i];
        } else if (sz == 512) {
            We = (const float*)d_in[i];
        } else if (sz > 2000000) {
            x = (const float*)d_in[i];
            x_elems = sz;
        } else {
            ei = (const int*)d_in[i];
            ei_elems = sz;
        }
    }

    const int n_nodes = x_elems / D;       // 50000
    const int n_edges = ei_elems / 2;      // 625000

    float* out = (float*)d_out;
    float* out_ne = out;
    float* out_ee = out_ne + (size_t)n_nodes * D;
    float* out_nx = out_ee + (size_t)n_edges * (2*D);
    float* out_ex = out_nx + (size_t)n_nodes * 2;

    const int threads = 256;
    const int blocks  = 148 * 8;   // 9472 warps

    gcn_fused_kernel<<<blocks, threads>>>(x, ei, Wn, bn, We, be,
                                          out_ne, out_nx, out_ee, out_ex,
                                          n_nodes, n_edges);
}